// round 1
// baseline (speedup 1.0000x reference)
#include <cuda_runtime.h>
#include <math.h>

#define NRENDER 16        // NF(2) * T(8)
#define NFACE_C 1024
#define NV_C 514
#define HW 128
#define TEXW 256
#define KSZ 11

// ---------------- device scratch (no allocations allowed) ----------------
__device__ float g_RT[NRENDER][12];            // 9 rotation + 3 translation
__device__ float g_gauss[KSZ];
__device__ float g_plane[NRENDER][NFACE_C][16]; // A0,B0,C0,A1,B1,C1,A2,B2,C2,zA,zB,zC,xmin,xmax,ymin,ymax
__device__ float g_uvp[NRENDER][NFACE_C][8];    // uA,uB,uC,vA,vB,vC,pad,pad
__device__ float g_img[NRENDER][4][HW][HW];     // rgb + raw mask
__device__ float g_maske[NRENDER][HW][HW];      // eroded / intermediate mask
__device__ float g_tmp[NRENDER][4][HW][HW];     // blur temp

// ---------------- setup: rotations, translations, gaussian ----------------
__device__ __forceinline__ void quat_to_R_dev(const float* q, float scale, float* R) {
    float c = q[0], x = q[1], y = q[2], z = q[3];
    float sin2 = x*x + y*y + z*z;
    float sint = sqrtf(fmaxf(sin2, 1e-12f));
    float tt = 2.0f * ((c < 0.0f) ? atan2f(-sint, -c) : atan2f(sint, c));
    float k = (sin2 > 1e-12f) ? (tt / sint) : 2.0f;
    float ax = k*x*scale, ay = k*y*scale, az = k*z*scale;
    float th = sqrtf(ax*ax + ay*ay + az*az);
    float inv = 1.0f / fmaxf(th, 1e-8f);
    float ux = ax*inv, uy = ay*inv, uz = az*inv;
    float s = sinf(th), co = cosf(th), oc = 1.0f - co;
    R[0] = 1.0f + oc*(-(uy*uy + uz*uz));
    R[1] = -s*uz + oc*(ux*uy);
    R[2] =  s*uy + oc*(ux*uz);
    R[3] =  s*uz + oc*(ux*uy);
    R[4] = 1.0f + oc*(-(ux*ux + uz*uz));
    R[5] = -s*ux + oc*(uy*uz);
    R[6] = -s*uy + oc*(ux*uz);
    R[7] =  s*ux + oc*(uy*uz);
    R[8] = 1.0f + oc*(-(ux*ux + uy*uy));
}

__global__ void setup_kernel(const float* __restrict__ quat, const float* __restrict__ trans) {
    int f = threadIdx.x;
    if (f == 0) {
        float g[KSZ]; float s = 0.0f;
        for (int k = 0; k < KSZ; k++) { float t = (float)k - 5.0f; g[k] = expf(-0.5f*t*t); s += g[k]; }
        for (int k = 0; k < KSZ; k++) g_gauss[k] = g[k] / s;
    }
    if (f < 2) {
        float R0[9], Rs[9];
        quat_to_R_dev(&quat[f*8 + 4], 1.0f, R0);         // q[:,f,1]
        quat_to_R_dev(&quat[f*8 + 0], 0.125f, Rs);       // q[:,f,0] / T / ROT_DIV
        float ts[3], td[3];
        for (int a = 0; a < 3; a++) { ts[a] = trans[a*4 + f*2 + 1]; td[a] = trans[a*4 + f*2 + 0]; }
        float Rm[9];
        for (int k = 0; k < 9; k++) Rm[k] = R0[k];
        for (int t = 0; t < 8; t++) {
            int r = f*8 + t;
            for (int k = 0; k < 9; k++) g_RT[r][k] = Rm[k];
            float ti = (float)t / 7.0f;
            for (int a = 0; a < 3; a++) g_RT[r][9+a] = ts[a] + ti*td[a];
            float Nw[9];
            for (int i = 0; i < 3; i++)
                for (int k = 0; k < 3; k++)
                    Nw[i*3+k] = Rm[i*3+0]*Rs[0*3+k] + Rm[i*3+1]*Rs[1*3+k] + Rm[i*3+2]*Rs[2*3+k];
            for (int k = 0; k < 9; k++) Rm[k] = Nw[k];
        }
    }
}

// ---------------- per (render, face) plane setup ----------------
__global__ void face_kernel(const float* __restrict__ verts, const int* __restrict__ faces,
                            const float* __restrict__ ff) {
    int gid = blockIdx.x * blockDim.x + threadIdx.x;
    if (gid >= NRENDER * NFACE_C) return;
    int r = gid >> 10, fc = gid & (NFACE_C - 1);
    float R[12];
    #pragma unroll
    for (int k = 0; k < 12; k++) R[k] = g_RT[r][k];
    const float invt = 1.0f / tanf(0.3925f);   // 1/tan(FOV/2), px==py since W/H==1
    float sx[3], sy[3], zz[3], P[3][3];
    #pragma unroll
    for (int k = 0; k < 3; k++) {
        int vi = faces[fc*3 + k];
        float vx = verts[vi*3+0], vy = verts[vi*3+1], vz = verts[vi*3+2];
        float Xc = R[0]*vx + R[1]*vy + R[2]*vz + R[9];
        float Yc = R[3]*vx + R[4]*vy + R[5]*vz + R[10];
        float Zc = R[6]*vx + R[7]*vy + R[8]*vz + R[11] - 2.0f;   // CAM_D
        P[k][0] = Xc; P[k][1] = Yc; P[k][2] = Zc;
        float nz_ = -Zc;
        sx[k] = (Xc * invt) / nz_;
        sy[k] = (Yc * invt) / nz_;
        zz[k] = Zc;
    }
    // camera-space face normal z (normalized)
    float e1x = P[1][0]-P[0][0], e1y = P[1][1]-P[0][1], e1z = P[1][2]-P[0][2];
    float e2x = P[2][0]-P[0][0], e2y = P[2][1]-P[0][1], e2z = P[2][2]-P[0][2];
    float nx = e1y*e2z - e1z*e2y;
    float ny = e1z*e2x - e1x*e2z;
    float nzv = e1x*e2y - e1y*e2x;
    float nz = nzv / (sqrtf(nx*nx + ny*ny + nzv*nzv) + 1e-8f);

    float area = (sx[1]-sx[0])*(sy[2]-sy[0]) - (sy[1]-sy[0])*(sx[2]-sx[0]);
    if (fabsf(area) < 1e-10f) area = 1e-10f;
    float A0 = -(sy[2]-sy[1])/area, B0 = (sx[2]-sx[1])/area;
    float C0 = ((sy[2]-sy[1])*sx[1] - (sx[2]-sx[1])*sy[1])/area;
    float A1 = -(sy[0]-sy[2])/area, B1 = (sx[0]-sx[2])/area;
    float C1 = ((sy[0]-sy[2])*sx[2] - (sx[0]-sx[2])*sy[2])/area;
    float A2 = -(sy[1]-sy[0])/area, B2 = (sx[1]-sx[0])/area;
    float C2 = ((sy[1]-sy[0])*sx[0] - (sx[1]-sx[0])*sy[0])/area;
    float zA = A0*zz[0] + A1*zz[1] + A2*zz[2];
    float zB = B0*zz[0] + B1*zz[1] + B2*zz[2];
    float zC = C0*zz[0] + C1*zz[1] + C2*zz[2];

    float xmin, xmax, ymin, ymax;
    if (nz > 0.0f) {
        xmin = fminf(sx[0], fminf(sx[1], sx[2]));
        xmax = fmaxf(sx[0], fmaxf(sx[1], sx[2]));
        ymin = fminf(sy[0], fminf(sy[1], sy[2]));
        ymax = fmaxf(sy[0], fmaxf(sy[1], sy[2]));
    } else {
        xmin = 1e30f; xmax = -1e30f; ymin = 1e30f; ymax = -1e30f;  // never passes cull
    }
    float* pl = g_plane[r][fc];
    pl[0]=A0; pl[1]=B0; pl[2]=C0; pl[3]=A1; pl[4]=B1; pl[5]=C1;
    pl[6]=A2; pl[7]=B2; pl[8]=C2; pl[9]=zA; pl[10]=zB; pl[11]=zC;
    pl[12]=xmin; pl[13]=xmax; pl[14]=ymin; pl[15]=ymax;

    float u0 = ff[fc*6+0], v0 = ff[fc*6+1];
    float u1 = ff[fc*6+2], v1 = ff[fc*6+3];
    float u2 = ff[fc*6+4], v2 = ff[fc*6+5];
    float* up = g_uvp[r][fc];
    up[0] = A0*u0 + A1*u1 + A2*u2;
    up[1] = B0*u0 + B1*u1 + B2*u2;
    up[2] = C0*u0 + C1*u1 + C2*u2;
    up[3] = A0*v0 + A1*v1 + A2*v2;
    up[4] = B0*v0 + B1*v1 + B2*v2;
    up[5] = C0*v0 + C1*v1 + C2*v2;
}

// ---------------- rasterize + texture sample ----------------
// grid: (64 tiles, 16 renders), block 256 = 16x16 pixels
__global__ void raster_kernel(const float* __restrict__ tex) {
    extern __shared__ float sm[];   // 1024 x 16 floats = 64KB compacted face store
    __shared__ int s_n;
    int r = blockIdx.y;
    int tile = blockIdx.x;
    int tx = tile & 7, ty = tile >> 3;
    int lj = threadIdx.x & 15, li = threadIdx.x >> 4;
    int j = tx*16 + lj, i = ty*16 + li;
    const float step = 2.0f / 127.0f;
    float X = -1.0f + (float)j * step;
    float Y =  1.0f - (float)i * step;
    float tXmin = -1.0f + (float)(tx*16) * step;
    float tXmax = -1.0f + (float)(tx*16 + 15) * step;
    float tYmax =  1.0f - (float)(ty*16) * step;
    float tYmin =  1.0f - (float)(ty*16 + 15) * step;

    if (threadIdx.x == 0) s_n = 0;
    __syncthreads();

    // tile cull + compaction
    for (int fc = threadIdx.x; fc < NFACE_C; fc += 256) {
        const float* pl = g_plane[r][fc];
        float4 bb = *(const float4*)(pl + 12);
        if (bb.x <= tXmax && bb.y >= tXmin && bb.z <= tYmax && bb.w >= tYmin) {
            int p = atomicAdd(&s_n, 1);
            float4 a = *(const float4*)(pl + 0);
            float4 b = *(const float4*)(pl + 4);
            float4 c = *(const float4*)(pl + 8);
            float* d = sm + p*16;
            *(float4*)(d + 0) = a;
            *(float4*)(d + 4) = b;
            *(float4*)(d + 8) = c;
            ((int*)d)[12] = fc;
        }
    }
    __syncthreads();
    int n = s_n;

    float best_z = -3.0e38f;
    int   best_f = 0x7fffffff;
    int   hit_i  = 0;
    for (int q = 0; q < n; q++) {
        const float* d = sm + q*16;
        float4 a = *(const float4*)(d + 0);
        float4 b = *(const float4*)(d + 4);
        float4 c = *(const float4*)(d + 8);
        int fidx = ((const int*)d)[12];
        float b0 = fmaf(a.x, X, fmaf(a.y, Y, a.z));
        float b1 = fmaf(a.w, X, fmaf(b.x, Y, b.y));
        float b2 = fmaf(b.z, X, fmaf(b.w, Y, c.x));
        float z  = fmaf(c.y, X, fmaf(c.z, Y, c.w));
        bool inside = (b0 >= 0.0f) && (b1 >= 0.0f) && (b2 >= 0.0f);
        if (inside) {
            hit_i = 1;
            if (z > best_z || (z == best_z && fidx < best_f)) { best_z = z; best_f = fidx; }
        }
    }

    float u = 0.0f, v = 0.0f;
    if (hit_i) {
        const float* up = g_uvp[r][best_f];
        u = fmaf(up[0], X, fmaf(up[1], Y, up[2]));
        v = fmaf(up[3], X, fmaf(up[4], Y, up[5]));
    }
    // bilinear sample (matches reference exactly, incl. miss -> uv=(0,0))
    float xf = u * 255.0f;
    float yf = (1.0f - v) * 255.0f;
    float x0 = fminf(fmaxf(floorf(xf), 0.0f), 254.0f);
    float y0 = fminf(fmaxf(floorf(yf), 0.0f), 254.0f);
    float fx = xf - x0, fy = yf - y0;
    int xi = (int)x0, yi = (int)y0;
    int base = yi * TEXW + xi;
    #pragma unroll
    for (int cch = 0; cch < 3; cch++) {
        const float* tc = tex + cch * (TEXW*TEXW);
        float t00 = __ldg(tc + base);
        float t01 = __ldg(tc + base + 1);
        float t10 = __ldg(tc + base + TEXW);
        float t11 = __ldg(tc + base + TEXW + 1);
        float val = t00*(1.0f-fx)*(1.0f-fy) + t01*fx*(1.0f-fy)
                  + t10*(1.0f-fx)*fy        + t11*fx*fy;
        g_img[r][cch][i][j] = val;
    }
    g_img[r][3][i][j] = (float)hit_i;
}

// ---------------- erode (3x3 min, SAME with +inf pad) ----------------
__global__ void erode_kernel() {
    int gid = blockIdx.x * blockDim.x + threadIdx.x;
    if (gid >= NRENDER * HW * HW) return;
    int r = gid >> 14, p = gid & 16383, i = p >> 7, j = p & 127;
    float m = 3.0e38f;
    #pragma unroll
    for (int di = -1; di <= 1; di++) {
        int ii = i + di; if (ii < 0 || ii > 127) continue;
        #pragma unroll
        for (int dj = -1; dj <= 1; dj++) {
            int jj = j + dj; if (jj < 0 || jj > 127) continue;
            m = fminf(m, g_img[r][3][ii][jj]);
        }
    }
    g_maske[r][i][j] = m;
}

// ---------------- separable blurs ----------------
__global__ void vblur4_kernel() {   // rgb from g_img, mask from g_maske -> g_tmp
    int gid = blockIdx.x * blockDim.x + threadIdx.x;
    if (gid >= NRENDER * 4 * HW * HW) return;
    int r = gid >> 16, c = (gid >> 14) & 3, i = (gid >> 7) & 127, j = gid & 127;
    const float* in = (c < 3) ? &g_img[r][c][0][0] : &g_maske[r][0][0];
    float acc = 0.0f;
    #pragma unroll
    for (int k = 0; k < KSZ; k++) {
        int ii = i + k - 5;
        if (ii >= 0 && ii < HW) acc = fmaf(g_gauss[k], in[ii*HW + j], acc);
    }
    g_tmp[r][c][i][j] = acc;
}

__global__ void hblur4_kernel(float* __restrict__ out) { // g_tmp -> out(rgb) / g_maske(mask)
    int gid = blockIdx.x * blockDim.x + threadIdx.x;
    if (gid >= NRENDER * 4 * HW * HW) return;
    int r = gid >> 16, c = (gid >> 14) & 3, i = (gid >> 7) & 127, j = gid & 127;
    const float* in = &g_tmp[r][c][0][0];
    float acc = 0.0f;
    #pragma unroll
    for (int k = 0; k < KSZ; k++) {
        int jj = j + k - 5;
        if (jj >= 0 && jj < HW) acc = fmaf(g_gauss[k], in[i*HW + jj], acc);
    }
    if (c < 3) out[(((r*4 + c) << 7) + i << 7) + j] = acc;
    else       g_maske[r][i][j] = acc;
}

__global__ void vblur1_kernel() {   // g_maske -> g_tmp[r][3]
    int gid = blockIdx.x * blockDim.x + threadIdx.x;
    if (gid >= NRENDER * HW * HW) return;
    int r = gid >> 14, p = gid & 16383, i = p >> 7, j = p & 127;
    const float* in = &g_maske[r][0][0];
    float acc = 0.0f;
    #pragma unroll
    for (int k = 0; k < KSZ; k++) {
        int ii = i + k - 5;
        if (ii >= 0 && ii < HW) acc = fmaf(g_gauss[k], in[ii*HW + j], acc);
    }
    g_tmp[r][3][i][j] = acc;
}

__global__ void hblur1_kernel(float* __restrict__ out) { // g_tmp[r][3] -> out mask channel
    int gid = blockIdx.x * blockDim.x + threadIdx.x;
    if (gid >= NRENDER * HW * HW) return;
    int r = gid >> 14, p = gid & 16383, i = p >> 7, j = p & 127;
    const float* in = &g_tmp[r][3][0][0];
    float acc = 0.0f;
    #pragma unroll
    for (int k = 0; k < KSZ; k++) {
        int jj = j + k - 5;
        if (jj >= 0 && jj < HW) acc = fmaf(g_gauss[k], in[i*HW + jj], acc);
    }
    out[((r*4 + 3) << 14) + (i << 7) + j] = acc;
}

// ---------------- launcher ----------------
extern "C" void kernel_launch(void* const* d_in, const int* in_sizes, int n_in,
                              void* d_out, int out_size) {
    const float* vertices  = (const float*)d_in[0];
    const float* quat      = (const float*)d_in[1];
    const float* trans     = (const float*)d_in[2];
    const float* face_ff   = (const float*)d_in[4];
    const float* tex       = (const float*)d_in[5];
    const int*   faces     = (const int*)d_in[6];
    float* out = (float*)d_out;

    static bool attr_set = false;
    if (!attr_set) {
        cudaFuncSetAttribute(raster_kernel, cudaFuncAttributeMaxDynamicSharedMemorySize, 65536);
        attr_set = true;
    }

    setup_kernel<<<1, 32>>>(quat, trans);
    face_kernel<<<(NRENDER*NFACE_C + 127)/128, 128>>>(vertices, faces, face_ff);
    raster_kernel<<<dim3(64, NRENDER), 256, 65536>>>(tex);
    erode_kernel<<<(NRENDER*HW*HW + 255)/256, 256>>>();
    vblur4_kernel<<<(NRENDER*4*HW*HW + 255)/256, 256>>>();
    hblur4_kernel<<<(NRENDER*4*HW*HW + 255)/256, 256>>>(out);
    vblur1_kernel<<<(NRENDER*HW*HW + 255)/256, 256>>>();
    hblur1_kernel<<<(NRENDER*HW*HW + 255)/256, 256>>>(out);
}